// round 6
// baseline (speedup 1.0000x reference)
#include <cuda_runtime.h>
#include <cuda_bf16.h>

// out[b, 1+d, p] = x[b, c, hx(p)*16+pi, hy(p)*16+pj] + pos[1+d, p]
//   where d = c*256 + pi*16 + pj, (hx,hy) = hilbert_d2xy(32, p)
// out[b, 0, e]   = cls[e] + pos[0, e]   (fused into ptile==0,dtile==0 CTA)
//
// Smem-free register transpose (R5) + occupancy push: 32-bit offsets and a
// loop-local epilogue shrink regs to <=32 so 8 CTAs/SM are resident. Every
// STG.128 covers a full 128B output line per 8-lane group.

__global__ __launch_bounds__(256, 8) void hilbert_main_kernel(
    const float* __restrict__ x,
    const float* __restrict__ cls,
    const float* __restrict__ pos,
    float* __restrict__ out)
{
    const int tid = threadIdx.x;
    const int w   = tid >> 5;          // warp 0..7  -> d-quads 4w..4w+3
    const int l   = tid & 31;

    const int ptile = blockIdx.x;      // 0..31
    const int dtile = blockIdx.y;      // 0..7
    const int b     = blockIdx.z;      // 0..63

    const int c   = dtile >> 1;        // channel
    const int pi0 = (dtile & 1) * 8;   // starting patch row within channel
    const int p0  = ptile * 32;
    const int d0  = dtile * 128;
    const int out_b = b * (1025 * 1024);   // 67.2M max: fits int32

    // Per-lane Hilbert d2xy for patch p0+l (N=32, 5 iterations)
    int pb;
    {
        int t = p0 + l;
        int hx = 0, hy = 0;
        #pragma unroll
        for (int s = 1; s < 32; s <<= 1) {
            int rx = 1 & (t >> 1);
            int ry = 1 & (t ^ rx);
            if (ry == 0) {
                if (rx == 1) { hx = s - 1 - hx; hy = s - 1 - hy; }
                int tmp = hx; hx = hy; hy = tmp;
            }
            hx += s * rx;
            hy += s * ry;
            t >>= 2;
        }
        pb = ((b * 4 + c) * 512 + hx * 16 + pi0) * 512 + hy * 16;
    }

    // Fused row0: out[b, 0, :] = cls + pos[0, :]  (one CTA per batch)
    if (ptile == 0 && dtile == 0) {
        float4 cv = *reinterpret_cast<const float4*>(cls + tid * 4);
        float4 pv = *reinterpret_cast<const float4*>(pos + tid * 4);
        cv.x += pv.x; cv.y += pv.y; cv.z += pv.z; cv.w += pv.w;
        *reinterpret_cast<float4*>(out + out_b + tid * 4) = cv;
    }

    const int q = l & 7;               // p-quad: patches 4q..4q+3
    const int s = l >> 3;              // sub-row selector
    // f = 4w + s : float4 slot within patch slab; d = 4f + j
    const int srcoff = w * 512 + s * 4;

    const int pb0 = __shfl_sync(0xffffffffu, pb, 4 * q + 0) + srcoff;
    const int pb1 = __shfl_sync(0xffffffffu, pb, 4 * q + 1) + srcoff;
    const int pb2 = __shfl_sync(0xffffffffu, pb, 4 * q + 2) + srcoff;
    const int pb3 = __shfl_sync(0xffffffffu, pb, 4 * q + 3) + srcoff;

    const float4 v0 = *reinterpret_cast<const float4*>(x + pb0);
    const float4 v1 = *reinterpret_cast<const float4*>(x + pb1);
    const float4 v2 = *reinterpret_cast<const float4*>(x + pb2);
    const float4 v3 = *reinterpret_cast<const float4*>(x + pb3);

    // Output rows 1 + d0 + 16w + 4s + j, cols p0 + 4q .. +3
    const int prow = (1 + d0 + 16 * w + 4 * s) * 1024 + (p0 + 4 * q);

    #pragma unroll
    for (int j = 0; j < 4; j++) {
        const float4 pe = *reinterpret_cast<const float4*>(pos + prow + j * 1024);
        float4 r;
        r.x = (j == 0 ? v0.x : j == 1 ? v0.y : j == 2 ? v0.z : v0.w) + pe.x;
        r.y = (j == 0 ? v1.x : j == 1 ? v1.y : j == 2 ? v1.z : v1.w) + pe.y;
        r.z = (j == 0 ? v2.x : j == 1 ? v2.y : j == 2 ? v2.z : v2.w) + pe.z;
        r.w = (j == 0 ? v3.x : j == 1 ? v3.y : j == 2 ? v3.z : v3.w) + pe.w;
        __stcs(reinterpret_cast<float4*>(out + out_b + prow + j * 1024), r);
    }
}

extern "C" void kernel_launch(void* const* d_in, const int* in_sizes, int n_in,
                              void* d_out, int out_size)
{
    // Identify inputs by size (defensive against ordering):
    //   x: 64*4*512*512 = 67108864, cls: 1024, pos: 1025*1024 = 1049600
    const float* x   = nullptr;
    const float* cls = nullptr;
    const float* pos = nullptr;
    for (int i = 0; i < n_in; i++) {
        if (in_sizes[i] == 67108864)     x   = (const float*)d_in[i];
        else if (in_sizes[i] == 1024)    cls = (const float*)d_in[i];
        else if (in_sizes[i] == 1049600) pos = (const float*)d_in[i];
    }
    float* out = (float*)d_out;

    dim3 grid(32, 8, 64);   // p-tiles, d-tiles, batch
    hilbert_main_kernel<<<grid, 256>>>(x, cls, pos, out);
}

// round 7
// speedup vs baseline: 1.1482x; 1.1482x over previous
#include <cuda_runtime.h>
#include <cuda_bf16.h>

// out[b, 1+d, p] = x[b, c, hx(p)*16+pi, hy(p)*16+pj] + pos[1+d, p]
//   where d = c*256 + pi*16 + pj, (hx,hy) = hilbert_d2xy(32, p)
// out[b, 0, e]   = cls[e] + pos[0, e]   (fused into ptile==0,dtile==0 CTA)
//
// Smem-free register transpose (R5) with 2 p-tiles per CTA: all 8 x-LDG.128s
// issued up front (MLP 8), tile-B's DRAM latency hides behind tile-A's
// epilogue. Batched pos loads + full-128B-line STG.128 per 8-lane group.

__device__ __forceinline__ int hilbert_base(int t, int b, int c, int pi0)
{
    int hx = 0, hy = 0;
    #pragma unroll
    for (int s = 1; s < 32; s <<= 1) {
        int rx = 1 & (t >> 1);
        int ry = 1 & (t ^ rx);
        if (ry == 0) {
            if (rx == 1) { hx = s - 1 - hx; hy = s - 1 - hy; }
            int tmp = hx; hx = hy; hy = tmp;
        }
        hx += s * rx;
        hy += s * ry;
        t >>= 2;
    }
    return ((b * 4 + c) * 512 + hx * 16 + pi0) * 512 + hy * 16;
}

__global__ __launch_bounds__(256) void hilbert_main_kernel(
    const float* __restrict__ x,
    const float* __restrict__ cls,
    const float* __restrict__ pos,
    float* __restrict__ out)
{
    const int tid = threadIdx.x;
    const int w   = tid >> 5;          // warp 0..7  -> d-quads 4w..4w+3
    const int l   = tid & 31;

    const int ptile = blockIdx.x;      // 0..15 (handles ptile and ptile+16)
    const int dtile = blockIdx.y;      // 0..7
    const int b     = blockIdx.z;      // 0..63

    const int c   = dtile >> 1;        // channel
    const int pi0 = (dtile & 1) * 8;   // starting patch row within channel
    const int p0  = ptile * 32;
    const int d0  = dtile * 128;
    const int out_b = b * (1025 * 1024);

    // Per-lane Hilbert bases: tile A patch p0+l, tile B patch p0+512+l
    const int pbA = hilbert_base(p0 + l,       b, c, pi0);
    const int pbB = hilbert_base(p0 + 512 + l, b, c, pi0);

    // Fused row0: out[b, 0, :] = cls + pos[0, :]  (one CTA per batch)
    if (ptile == 0 && dtile == 0) {
        float4 cv = *reinterpret_cast<const float4*>(cls + tid * 4);
        float4 pv = *reinterpret_cast<const float4*>(pos + tid * 4);
        cv.x += pv.x; cv.y += pv.y; cv.z += pv.z; cv.w += pv.w;
        *reinterpret_cast<float4*>(out + out_b + tid * 4) = cv;
    }

    const int q = l & 7;               // p-quad: patches 4q..4q+3
    const int s = l >> 3;              // sub-row selector
    // f = 4w + s : float4 slot within patch slab; d = 4f + j
    const int srcoff = w * 512 + s * 4;

    const int a0 = __shfl_sync(0xffffffffu, pbA, 4 * q + 0) + srcoff;
    const int a1 = __shfl_sync(0xffffffffu, pbA, 4 * q + 1) + srcoff;
    const int a2 = __shfl_sync(0xffffffffu, pbA, 4 * q + 2) + srcoff;
    const int a3 = __shfl_sync(0xffffffffu, pbA, 4 * q + 3) + srcoff;
    const int b0 = __shfl_sync(0xffffffffu, pbB, 4 * q + 0) + srcoff;
    const int b1 = __shfl_sync(0xffffffffu, pbB, 4 * q + 1) + srcoff;
    const int b2 = __shfl_sync(0xffffffffu, pbB, 4 * q + 2) + srcoff;
    const int b3 = __shfl_sync(0xffffffffu, pbB, 4 * q + 3) + srcoff;

    // All 8 x loads in flight before any consumption (MLP 8)
    const float4 v0 = *reinterpret_cast<const float4*>(x + a0);
    const float4 v1 = *reinterpret_cast<const float4*>(x + a1);
    const float4 v2 = *reinterpret_cast<const float4*>(x + a2);
    const float4 v3 = *reinterpret_cast<const float4*>(x + a3);
    const float4 u0 = *reinterpret_cast<const float4*>(x + b0);
    const float4 u1 = *reinterpret_cast<const float4*>(x + b1);
    const float4 u2 = *reinterpret_cast<const float4*>(x + b2);
    const float4 u3 = *reinterpret_cast<const float4*>(x + b3);

    // Output rows 1 + d0 + 16w + 4s + j; tile A cols p0+4q, tile B +512
    const int prow = (1 + d0 + 16 * w + 4 * s) * 1024 + (p0 + 4 * q);

    // ---- Tile A epilogue: 4 batched pos loads, 4 full-line stores ----
    {
        const float4 pe0 = *reinterpret_cast<const float4*>(pos + prow);
        const float4 pe1 = *reinterpret_cast<const float4*>(pos + prow + 1024);
        const float4 pe2 = *reinterpret_cast<const float4*>(pos + prow + 2048);
        const float4 pe3 = *reinterpret_cast<const float4*>(pos + prow + 3072);
        float4 r;
        r = make_float4(v0.x + pe0.x, v1.x + pe0.y, v2.x + pe0.z, v3.x + pe0.w);
        __stcs(reinterpret_cast<float4*>(out + out_b + prow), r);
        r = make_float4(v0.y + pe1.x, v1.y + pe1.y, v2.y + pe1.z, v3.y + pe1.w);
        __stcs(reinterpret_cast<float4*>(out + out_b + prow + 1024), r);
        r = make_float4(v0.z + pe2.x, v1.z + pe2.y, v2.z + pe2.z, v3.z + pe2.w);
        __stcs(reinterpret_cast<float4*>(out + out_b + prow + 2048), r);
        r = make_float4(v0.w + pe3.x, v1.w + pe3.y, v2.w + pe3.z, v3.w + pe3.w);
        __stcs(reinterpret_cast<float4*>(out + out_b + prow + 3072), r);
    }

    // ---- Tile B epilogue ----
    {
        const int prowB = prow + 512;
        const float4 pe0 = *reinterpret_cast<const float4*>(pos + prowB);
        const float4 pe1 = *reinterpret_cast<const float4*>(pos + prowB + 1024);
        const float4 pe2 = *reinterpret_cast<const float4*>(pos + prowB + 2048);
        const float4 pe3 = *reinterpret_cast<const float4*>(pos + prowB + 3072);
        float4 r;
        r = make_float4(u0.x + pe0.x, u1.x + pe0.y, u2.x + pe0.z, u3.x + pe0.w);
        __stcs(reinterpret_cast<float4*>(out + out_b + prowB), r);
        r = make_float4(u0.y + pe1.x, u1.y + pe1.y, u2.y + pe1.z, u3.y + pe1.w);
        __stcs(reinterpret_cast<float4*>(out + out_b + prowB + 1024), r);
        r = make_float4(u0.z + pe2.x, u1.z + pe2.y, u2.z + pe2.z, u3.z + pe2.w);
        __stcs(reinterpret_cast<float4*>(out + out_b + prowB + 2048), r);
        r = make_float4(u0.w + pe3.x, u1.w + pe3.y, u2.w + pe3.z, u3.w + pe3.w);
        __stcs(reinterpret_cast<float4*>(out + out_b + prowB + 3072), r);
    }
}

extern "C" void kernel_launch(void* const* d_in, const int* in_sizes, int n_in,
                              void* d_out, int out_size)
{
    // Identify inputs by size (defensive against ordering):
    //   x: 64*4*512*512 = 67108864, cls: 1024, pos: 1025*1024 = 1049600
    const float* x   = nullptr;
    const float* cls = nullptr;
    const float* pos = nullptr;
    for (int i = 0; i < n_in; i++) {
        if (in_sizes[i] == 67108864)     x   = (const float*)d_in[i];
        else if (in_sizes[i] == 1024)    cls = (const float*)d_in[i];
        else if (in_sizes[i] == 1049600) pos = (const float*)d_in[i];
    }
    float* out = (float*)d_out;

    dim3 grid(16, 8, 64);   // p-tile pairs, d-tiles, batch
    hilbert_main_kernel<<<grid, 256>>>(x, cls, pos, out);
}